// round 1
// baseline (speedup 1.0000x reference)
#include <cuda_runtime.h>
#include <cuda_bf16.h>

// Problem constants
#define BB 65536
#define VV 4
#define JJ 32

// Scratch for per-batch partial sums (no allocation allowed -> device global)
__device__ float g_partials[BB];

__device__ __forceinline__ float warp_sum(float v) {
#pragma unroll
    for (int o = 16; o; o >>= 1) v += __shfl_xor_sync(0xFFFFFFFFu, v, o);
    return v;
}

// One block per batch b. 128 threads = 4 warps; warp v handles view v, lane = joint j.
__global__ __launch_bounds__(128) void proj_loss_main(
    const float* __restrict__ Kmat,        // (B,V,3,3)
    const float* __restrict__ cam,         // (B,V,3,4)
    const float* __restrict__ kw,          // (B,J,3)
    const float* __restrict__ ik)          // (B,V,J,2)
{
    const int b    = blockIdx.x;
    const int tid  = threadIdx.x;
    const int warp = tid >> 5;   // view index
    const int lane = tid & 31;   // joint index

    __shared__ float s_kw[JJ * 3];     // 96
    __shared__ float s_cam[VV * 12];   // 48
    __shared__ float s_K[VV * 9];      // 36
    __shared__ float s_pv[VV];

    // Stage per-batch data, all contiguous & coalesced
    if (tid < JJ * 3)   s_kw[tid]  = kw[(size_t)b * (JJ * 3) + tid];
    if (tid < VV * 12)  s_cam[tid] = cam[(size_t)b * (VV * 12) + tid];
    if (tid < VV * 9)   s_K[tid]   = Kmat[(size_t)b * (VV * 9) + tid];
    __syncthreads();

    // Per-view camera (uniform across warp; shared reads broadcast)
    const float* cv = &s_cam[warp * 12];
    const float R00 = cv[0], R01 = cv[1], R02 = cv[2],  t0 = cv[3];
    const float R10 = cv[4], R11 = cv[5], R12 = cv[6],  t1 = cv[7];
    const float R20 = cv[8], R21 = cv[9], R22 = cv[10], t2 = cv[11];

    const float* kv = &s_K[warp * 9];
    const float K00 = kv[0], K01 = kv[1], c0 = kv[2];
    const float K10 = kv[3], K11 = kv[4], c1 = kv[5];

    // Joint world position (stride-3 shared reads: conflict-free, gcd(3,32)=1)
    const float X0 = s_kw[lane * 3 + 0];
    const float X1 = s_kw[lane * 3 + 1];
    const float X2 = s_kw[lane * 3 + 2];

    // Camera-space point
    const float Xc0 = fmaf(R00, X0, fmaf(R01, X1, fmaf(R02, X2, t0)));
    const float Xc1 = fmaf(R10, X0, fmaf(R11, X1, fmaf(R12, X2, t1)));
    const float Xc2 = fmaf(R20, X0, fmaf(R21, X1, fmaf(R22, X2, t2)));

    // Shared mean depth across the 32 joints
    const float zbar  = warp_sum(Xc2) * (1.0f / 32.0f);
    const float inv_z = 1.0f / zbar;

    const float x = Xc0 * inv_z;
    const float y = Xc1 * inv_z;

    // uv = K[:2,:2] @ xy + c
    const float ux = fmaf(K00, x, fmaf(K01, y, c0));
    const float uy = fmaf(K10, x, fmaf(K11, y, c1));

    // initial keypoints: coalesced float2
    const float2 ikv = reinterpret_cast<const float2*>(ik)
        [((size_t)b * VV + warp) * JJ + lane];

    // Frobenius norms over (J,2)
    const float np2 = warp_sum(fmaf(ux, ux, uy * uy));
    const float ni2 = warp_sum(fmaf(ikv.x, ikv.x, ikv.y * ikv.y));
    const float rp  = rsqrtf(np2);
    const float ri  = rsqrtf(ni2);

    const float d = fabsf(fmaf(ux, rp, -ikv.x * ri)) +
                    fabsf(fmaf(uy, rp, -ikv.y * ri));
    const float pv = warp_sum(d) * (1.0f / 64.0f);   // mean over (J,2)

    if (lane == 0) s_pv[warp] = pv;
    __syncthreads();
    if (tid == 0)
        g_partials[b] = s_pv[0] + s_pv[1] + s_pv[2] + s_pv[3];
}

// Deterministic final reduction: 1 block, 1024 threads, fixed order.
__global__ __launch_bounds__(1024) void proj_loss_reduce(float* __restrict__ out)
{
    __shared__ float s[1024];
    const int t = threadIdx.x;
    float a = 0.0f;
#pragma unroll
    for (int i = 0; i < BB / 1024; ++i)
        a += g_partials[t * (BB / 1024) + i];
    s[t] = a;
    __syncthreads();
#pragma unroll
    for (int o = 512; o; o >>= 1) {
        if (t < o) s[t] += s[t + o];
        __syncthreads();
    }
    if (t == 0) out[0] = s[0] * (1.0f / ((float)BB * (float)VV));
}

extern "C" void kernel_launch(void* const* d_in, const int* in_sizes, int n_in,
                              void* d_out, int out_size)
{
    const float* Kmat = (const float*)d_in[0];  // (B,V,3,3)
    const float* cam  = (const float*)d_in[1];  // (B,V,3,4)
    const float* kw   = (const float*)d_in[2];  // (B,J,3)
    const float* ik   = (const float*)d_in[3];  // (B,V,J,2)
    float* out = (float*)d_out;

    proj_loss_main<<<BB, 128>>>(Kmat, cam, kw, ik);
    proj_loss_reduce<<<1, 1024>>>(out);
}

// round 2
// speedup vs baseline: 1.7684x; 1.7684x over previous
#include <cuda_runtime.h>
#include <cuda_bf16.h>

#define BB 65536
#define VV 4
#define JJ 32

#define NB 4                 // batches per warp
#define WPB 8                // warps per block
#define NBLK (BB / (NB * WPB))   // 2048 blocks

__device__ float g_partials[NBLK];

__device__ __forceinline__ float warp_sum(float v) {
#pragma unroll
    for (int o = 16; o; o >>= 1) v += __shfl_xor_sync(0xFFFFFFFFu, v, o);
    return v;
}

// Each warp processes NB consecutive batches, all 4 views each.
// Per-warp shared staging slice; only __syncwarp in the hot loop.
__global__ __launch_bounds__(WPB * 32) void proj_loss_main(
    const float* __restrict__ Kmat,        // (B,V,3,3)
    const float* __restrict__ cam,         // (B,V,3,4)
    const float* __restrict__ kw,          // (B,J,3)
    const float* __restrict__ ik)          // (B,V,J,2)
{
    const int warp = threadIdx.x >> 5;
    const int lane = threadIdx.x & 31;
    const int gw   = blockIdx.x * WPB + warp;

    // per-warp slice: [0:96) kw, [96:144) cam, [144:180) K; pad to 192
    __shared__ float s_stage[WPB][192];
    __shared__ float s_part[WPB];
    float* st = s_stage[warp];

    float acc = 0.0f;
    const int b0 = gw * NB;

#pragma unroll 1
    for (int ib = 0; ib < NB; ++ib) {
        const int b = b0 + ib;
        const float* kwp  = kw   + (size_t)b * (JJ * 3);
        const float* camp = cam  + (size_t)b * (VV * 12);
        const float* Kp   = Kmat + (size_t)b * (VV * 9);

        __syncwarp();  // previous iteration done reading the slice
        st[lane]       = kwp[lane];
        st[32 + lane]  = kwp[32 + lane];
        st[64 + lane]  = kwp[64 + lane];
        st[96 + lane]  = camp[lane];
        if (lane < 16) st[128 + lane] = camp[32 + lane];
        st[144 + lane] = Kp[lane];
        if (lane < 4)  st[176 + lane] = Kp[32 + lane];
        __syncwarp();

        // Joint world position for this lane's joint (stride-3: conflict-free)
        const float X0 = st[lane * 3 + 0];
        const float X1 = st[lane * 3 + 1];
        const float X2 = st[lane * 3 + 2];

        const float2* ikb = reinterpret_cast<const float2*>(ik) + (size_t)b * (VV * JJ);

#pragma unroll
        for (int v = 0; v < VV; ++v) {
            const float* cv = &st[96 + v * 12];
            const float R00 = cv[0], R01 = cv[1], R02 = cv[2],  t0 = cv[3];
            const float R10 = cv[4], R11 = cv[5], R12 = cv[6],  t1 = cv[7];
            const float R20 = cv[8], R21 = cv[9], R22 = cv[10], t2 = cv[11];

            const float* kvp = &st[144 + v * 9];
            const float K00 = kvp[0], K01 = kvp[1], c0 = kvp[2];
            const float K10 = kvp[3], K11 = kvp[4], c1 = kvp[5];

            const float Xc0 = fmaf(R00, X0, fmaf(R01, X1, fmaf(R02, X2, t0)));
            const float Xc1 = fmaf(R10, X0, fmaf(R11, X1, fmaf(R12, X2, t1)));
            const float Xc2 = fmaf(R20, X0, fmaf(R21, X1, fmaf(R22, X2, t2)));

            const float zbar  = warp_sum(Xc2) * (1.0f / 32.0f);
            const float inv_z = 1.0f / zbar;

            const float x = Xc0 * inv_z;
            const float y = Xc1 * inv_z;

            const float ux = fmaf(K00, x, fmaf(K01, y, c0));
            const float uy = fmaf(K10, x, fmaf(K11, y, c1));

            const float2 ikv = ikb[v * JJ + lane];

            const float np2 = warp_sum(fmaf(ux, ux, uy * uy));
            const float ni2 = warp_sum(fmaf(ikv.x, ikv.x, ikv.y * ikv.y));
            const float rp  = rsqrtf(np2);
            const float ri  = rsqrtf(ni2);

            const float d = fabsf(fmaf(ux, rp, -ikv.x * ri)) +
                            fabsf(fmaf(uy, rp, -ikv.y * ri));
            acc += warp_sum(d);
        }
    }

    acc *= (1.0f / 64.0f);   // mean over (J,2) per view

    if (lane == 0) s_part[warp] = acc;
    __syncthreads();
    if (threadIdx.x == 0) {
        float s = 0.0f;
#pragma unroll
        for (int i = 0; i < WPB; ++i) s += s_part[i];
        g_partials[blockIdx.x] = s;
    }
}

// Deterministic final reduction over 2048 partials: 1 block, 1024 threads.
__global__ __launch_bounds__(1024) void proj_loss_reduce(float* __restrict__ out)
{
    __shared__ float s[1024];
    const int t = threadIdx.x;
    s[t] = g_partials[t] + g_partials[t + 1024];
    __syncthreads();
#pragma unroll
    for (int o = 512; o; o >>= 1) {
        if (t < o) s[t] += s[t + o];
        __syncthreads();
    }
    if (t == 0) out[0] = s[0] * (1.0f / ((float)BB * (float)VV));
}

extern "C" void kernel_launch(void* const* d_in, const int* in_sizes, int n_in,
                              void* d_out, int out_size)
{
    const float* Kmat = (const float*)d_in[0];  // (B,V,3,3)
    const float* cam  = (const float*)d_in[1];  // (B,V,3,4)
    const float* kw   = (const float*)d_in[2];  // (B,J,3)
    const float* ik   = (const float*)d_in[3];  // (B,V,J,2)
    float* out = (float*)d_out;

    proj_loss_main<<<NBLK, WPB * 32>>>(Kmat, cam, kw, ik);
    proj_loss_reduce<<<1, 1024>>>(out);
}

// round 3
// speedup vs baseline: 3.1946x; 1.8064x over previous
#include <cuda_runtime.h>
#include <cuda_bf16.h>

#define BB 65536
#define VV 4
#define BPB 32                       // batches per block
#define THREADS 128                  // one thread per (batch, view)
#define NBLK (BB / BPB)              // 2048

// shared-memory layout (floats), padded strides for bank-conflict avoidance
#define CAM_OFF 3200                 // kw: 32 batches x stride 100
#define KK_OFF  4864                 // cam: 32 x stride 52
#define IK_OFF  6272                 // K:  32 x stride 44
#define SMEM_FLOATS 14720            // ik: 128 tasks x stride 66
#define SMEM_BYTES (SMEM_FLOATS * 4)

__device__ float g_partials[NBLK];
__device__ unsigned int g_ticket;    // zero-initialized; restored to 0 each run

static __device__ __forceinline__ float warp_sum(float v) {
#pragma unroll
    for (int o = 16; o; o >>= 1) v += __shfl_xor_sync(0xFFFFFFFFu, v, o);
    return v;
}

__global__ __launch_bounds__(THREADS) void proj_loss(
    const float* __restrict__ Kmat,   // (B,V,3,3)
    const float* __restrict__ cam,    // (B,V,3,4)
    const float* __restrict__ kw,     // (B,J,3)
    const float* __restrict__ ik,     // (B,V,J,2)
    float* __restrict__ out)
{
    extern __shared__ float sm[];
    __shared__ float s_w[4];
    __shared__ int s_last;

    const int tid = threadIdx.x;
    const int b0 = blockIdx.x * BPB;

    // ---------------- stage to smem, fully coalesced float4 ----------------
    {
        const float4* g = (const float4*)(kw + (size_t)b0 * 96);   // 768 f4
#pragma unroll
        for (int r = 0; r < 6; ++r) {
            int i = tid + r * 128;
            int b = i / 24, k = i - b * 24;
            *(float4*)&sm[b * 100 + k * 4] = __ldcs(&g[i]);
        }
    }
    {
        const float4* g = (const float4*)(cam + (size_t)b0 * 48);  // 384 f4
#pragma unroll
        for (int r = 0; r < 3; ++r) {
            int i = tid + r * 128;
            int b = i / 12, k = i - b * 12;
            *(float4*)&sm[CAM_OFF + b * 52 + k * 4] = __ldcs(&g[i]);
        }
    }
    {
        const float4* g = (const float4*)(Kmat + (size_t)b0 * 36); // 288 f4
#pragma unroll
        for (int r = 0; r < 3; ++r) {
            int i = tid + r * 128;
            if (i < 288) {
                int b = i / 9, k = i - b * 9;
                *(float4*)&sm[KK_OFF + b * 44 + k * 4] = __ldcs(&g[i]);
            }
        }
    }
    {
        const float4* g = (const float4*)(ik + (size_t)b0 * 256);  // 2048 f4
#pragma unroll
        for (int r = 0; r < 16; ++r) {
            int i = tid + r * 128;
            int t = i >> 4, jp = i & 15;           // 16 f4 per task
            float4 val = __ldcs(&g[i]);
            int base = IK_OFF + t * 66 + jp * 4;
            *(float2*)&sm[base]     = make_float2(val.x, val.y);
            *(float2*)&sm[base + 2] = make_float2(val.z, val.w);
        }
    }
    __syncthreads();

    // ---------------- one task per thread: task = (bl, v) -------------------
    const int bl = tid >> 2, v = tid & 3;
    const float* cv = &sm[CAM_OFF + bl * 52 + v * 12];
    const float R00=cv[0], R01=cv[1], R02=cv[2],  t0=cv[3];
    const float R10=cv[4], R11=cv[5], R12=cv[6],  t1=cv[7];
    const float R20=cv[8], R21=cv[9], R22=cv[10], t2=cv[11];
    const float* kp = &sm[KK_OFF + bl * 44 + v * 9];
    const float K00=kp[0], K01=kp[1], c0=kp[2];
    const float K10=kp[3], K11=kp[4], c1=kp[5];

    const float* X = &sm[bl * 100];
    const float2* ikp = (const float2*)&sm[IK_OFF + tid * 66];

    // pass A: component sums of world keypoints -> zbar = R2.(S/32) + t2
    float Sx = 0.f, Sy = 0.f, Sz = 0.f;
#pragma unroll
    for (int g = 0; g < 8; ++g) {   // 4 joints (12 floats = 3 f4) per group
        float4 p0 = *(const float4*)&X[g*12];
        float4 p1 = *(const float4*)&X[g*12+4];
        float4 p2 = *(const float4*)&X[g*12+8];
        Sx += p0.x + p0.w + p1.z + p2.y;
        Sy += p0.y + p1.x + p1.w + p2.z;
        Sz += p0.z + p1.y + p2.x + p2.w;
    }
    const float zbar = fmaf(R20, Sx, fmaf(R21, Sy, R22 * Sz)) * (1.0f/32.0f) + t2;
    const float izb  = __fdividef(1.0f, zbar);

    // fold K * R * inv_z into 6 coeffs + 2 offsets: uv = a.X + b
    const float a0x = izb * fmaf(K00, R00, K01 * R10);
    const float a0y = izb * fmaf(K00, R01, K01 * R11);
    const float a0z = izb * fmaf(K00, R02, K01 * R12);
    const float b0u = fmaf(izb, fmaf(K00, t0, K01 * t1), c0);
    const float a1x = izb * fmaf(K10, R00, K11 * R10);
    const float a1y = izb * fmaf(K10, R01, K11 * R11);
    const float a1z = izb * fmaf(K10, R02, K11 * R12);
    const float b1u = fmaf(izb, fmaf(K10, t0, K11 * t1), c1);

    // pass B: uv per joint (kept in regs) + both squared norms
    float2 uv[32];
    float np2 = 0.f, ni2 = 0.f;
#pragma unroll
    for (int g = 0; g < 8; ++g) {
        float4 p0 = *(const float4*)&X[g*12];
        float4 p1 = *(const float4*)&X[g*12+4];
        float4 p2 = *(const float4*)&X[g*12+8];
        float xs[4] = {p0.x, p0.w, p1.z, p2.y};
        float ys[4] = {p0.y, p1.x, p1.w, p2.z};
        float zs[4] = {p0.z, p1.y, p2.x, p2.w};
#pragma unroll
        for (int q = 0; q < 4; ++q) {
            int j = g * 4 + q;
            float ux = fmaf(a0x, xs[q], fmaf(a0y, ys[q], fmaf(a0z, zs[q], b0u)));
            float uy = fmaf(a1x, xs[q], fmaf(a1y, ys[q], fmaf(a1z, zs[q], b1u)));
            uv[j] = make_float2(ux, uy);
            np2 = fmaf(ux, ux, fmaf(uy, uy, np2));
            float2 qv = ikp[j];
            ni2 = fmaf(qv.x, qv.x, fmaf(qv.y, qv.y, ni2));
        }
    }
    const float rp = rsqrtf(np2);
    const float ri = rsqrtf(ni2);

    // pass C: L1 of scale-free difference
    float acc = 0.f;
#pragma unroll
    for (int j = 0; j < 32; ++j) {
        float2 qv = ikp[j];
        acc += fabsf(fmaf(uv[j].x, rp, -qv.x * ri))
             + fabsf(fmaf(uv[j].y, rp, -qv.y * ri));
    }

    // ---------------- block partial (few shuffles, negligible now) ----------
    acc = warp_sum(acc);
    if ((tid & 31) == 0) s_w[tid >> 5] = acc;
    __syncthreads();
    if (tid == 0) {
        float bsum = s_w[0] + s_w[1] + s_w[2] + s_w[3];
        __stcg(&g_partials[blockIdx.x], bsum);
        __threadfence();
        unsigned int t = atomicAdd(&g_ticket, 1u);
        s_last = (t == NBLK - 1u);
    }
    __syncthreads();

    // ---------------- last block: deterministic final reduction -------------
    if (s_last) {
        float a = 0.f;
#pragma unroll
        for (int i = 0; i < NBLK / THREADS; ++i)       // 16 contiguous per thread
            a += __ldcg(&g_partials[tid * (NBLK / THREADS) + i]);
        a = warp_sum(a);
        if ((tid & 31) == 0) s_w[tid >> 5] = a;
        __syncthreads();
        if (tid == 0) {
            float tot = s_w[0] + s_w[1] + s_w[2] + s_w[3];
            out[0] = tot * (1.0f / (64.0f * (float)BB * (float)VV));
            g_ticket = 0u;                              // reset for next replay
        }
    }
}

extern "C" void kernel_launch(void* const* d_in, const int* in_sizes, int n_in,
                              void* d_out, int out_size)
{
    const float* Kmat = (const float*)d_in[0];  // (B,V,3,3)
    const float* cam  = (const float*)d_in[1];  // (B,V,3,4)
    const float* kw   = (const float*)d_in[2];  // (B,J,3)
    const float* ik   = (const float*)d_in[3];  // (B,V,J,2)
    float* out = (float*)d_out;

    cudaFuncSetAttribute(proj_loss, cudaFuncAttributeMaxDynamicSharedMemorySize, SMEM_BYTES);
    proj_loss<<<NBLK, THREADS, SMEM_BYTES>>>(Kmat, cam, kw, ik, out);
}